// round 1
// baseline (speedup 1.0000x reference)
#include <cuda_runtime.h>

// NPZD Euler integration: 1024*52 independent chains of 168 steps.
// t_idx[w,j] = 168*w + j exactly, so f/delta gathers are contiguous windows.
// One thread per (b,w) pair; f/delta staged through SMEM in 4 chunks of 42
// steps with coalesced float2 loads (pitch-43 SMEM rows -> conflict-free LDS).

#define BB 1024
#define WW 52
#define HOURS 8760
#define TSTEPS 168
#define PAIRS (BB * WW)        // 53248
#define TPB 128
#define CHUNK 42
#define NCHUNK 4               // 4 * 42 = 168
#define PITCH 43               // odd -> gcd(43,32)=1 -> conflict-free LDS

__global__ __launch_bounds__(TPB) void npzd_kernel(
    const float* __restrict__ X_in,      // (B, W, 5, 1)
    const float* __restrict__ gf,        // (B, HOURS)
    const float* __restrict__ gd,        // (B, HOURS)
    const float* __restrict__ params,    // (B, 10)
    float* __restrict__ out)             // (B, W, 4, 8)
{
    __shared__ float fsm[TPB * PITCH];
    __shared__ float dsm[TPB * PITCH];
    __shared__ int   bases[TPB];

    const int t = threadIdx.x;
    const int p = blockIdx.x * TPB + t;      // pair index, exact grid
    const int b = p / WW;
    const int w = p - b * WW;

    bases[t] = b * HOURS + w * TSTEPS;       // contiguous 168-float window start

    const float dt  = 1.0f / 24.0f;
    const float thr = 0.01f;

    const float* pp = params + b * 10;
    const float Kn    = pp[0] * 1.0f;
    const float Rm    = pp[1] * 2.0f;
    const float gz    = pp[2] * 0.1f;
    const float lam   = pp[3] * 0.05f;
    const float eps   = pp[4] * 0.1f;
    const float alpha = pp[5] * 0.3f;
    const float beta  = pp[6] * 0.6f;
    const float rr    = pp[7] * 0.15f;
    const float phi   = pp[8] * 0.4f;
    const float Sw    = pp[9] * 0.1f;

    // fold dt into coefficients once
    const float dta   = dt * alpha;
    const float dte   = dt * eps;
    const float dtg   = dt * gz;
    const float dtphi = dt * phi;
    const float dtb   = dt * beta;
    const float dtr   = dt * rr;
    const float dtab  = dt * (1.0f - alpha - beta);
    const float cp    = dt * (eps + rr);
    const float cd    = dt * (phi + Sw);

    // initial states: X_in[(p)*5 + {1..4}]
    const float* xi = X_in + (size_t)p * 5;
    float N = xi[1];
    float P = xi[2];
    float Z = xi[3];
    float D = xi[4];

    float* op = out + (size_t)p * 32;        // [4 states][8 samples]
    op[0]  = N;
    op[8]  = P;
    op[16] = Z;
    op[24] = D;

    float gam = __fdividef(N, Kn + N);
    float zoo = Rm * (1.0f - __expf(-lam * fmaxf(thr, P))) * fmaxf(thr, Z);

    const int fb = t * PITCH;
    int jnext = 23;   // store after steps 24,48,...,168 (0-based j = 23,...,167)
    int k = 1;

    for (int c = 0; c < NCHUNK; ++c) {
        __syncthreads();   // also covers bases[] visibility on c==0
        // cooperative chunk load: 128 pairs x 42 floats, float2-granular.
        // bases are even and chunk offsets even -> 8B aligned.
        const int cbase = c * CHUNK;
        #pragma unroll
        for (int r = 0; r < (CHUNK / 2); ++r) {
            int i = r * TPB + t;             // 0 .. 2687
            int q = i / (CHUNK / 2);         // pair slot in block
            int e = i - q * (CHUNK / 2);     // float2 index within chunk
            int g = bases[q] + cbase + e * 2;
            float2 fv = *reinterpret_cast<const float2*>(gf + g);
            float2 dv = *reinterpret_cast<const float2*>(gd + g);
            int so = q * PITCH + e * 2;
            fsm[so]     = fv.x;
            fsm[so + 1] = fv.y;
            dsm[so]     = dv.x;
            dsm[so + 1] = dv.y;
        }
        __syncthreads();

        #pragma unroll
        for (int jj = 0; jj < CHUNK; ++jj) {
            const float ft = fsm[fb + jj];
            const float dl = dsm[fb + jj];
            const float mP = fmaxf(thr, P);
            const float up = gam * ft * mP;          // Vm = 1
            const float dd = dt * dl;

            float N1 = fmaf(-dt,   up,  N);
            N1 = fmaf(dta,   zoo,      N1);
            N1 = fmaf(dte,   P,        N1);
            N1 = fmaf(dtg,   Z,        N1);
            N1 = fmaf(dtphi, D,        N1);
            N1 = fmaf(dd,    8.0f - N, N1);          // Q0 = 8

            float P1 = fmaf(dt, up, P);
            P1 = fmaf(-dt, zoo, P1);
            P1 = fmaf(-cp, P,   P1);
            P1 = fmaf(-dd, P,   P1);

            float Z1 = fmaf(dtb,  zoo, Z);
            Z1 = fmaf(-dtg, Z, Z1);
            Z1 = fmaf(-dd,  Z, Z1);

            float D1 = fmaf(dtr,  P,   D);
            D1 = fmaf(dtab, zoo, D1);
            D1 = fmaf(-cd,  D,   D1);
            D1 = fmaf(-dd,  D,   D1);

            N = N1; P = P1; Z = Z1; D = D1;

            gam = __fdividef(N1, Kn + N1);
            const float ex = __expf(-lam * fmaxf(thr, P1));
            zoo = Rm * (1.0f - ex) * fmaxf(thr, Z1);

            const int j = cbase + jj;
            if (j == jnext) {
                op[k]      = N1;
                op[8 + k]  = P1;
                op[16 + k] = Z1;
                op[24 + k] = D1;
                jnext += 24;
                ++k;
            }
        }
    }
}

extern "C" void kernel_launch(void* const* d_in, const int* in_sizes, int n_in,
                              void* d_out, int out_size) {
    const float* X_in  = (const float*)d_in[0];
    const float* gf    = (const float*)d_in[1];
    const float* gd    = (const float*)d_in[2];
    const float* par   = (const float*)d_in[3];
    float* out = (float*)d_out;

    npzd_kernel<<<PAIRS / TPB, TPB>>>(X_in, gf, gd, par, out);
}